// round 9
// baseline (speedup 1.0000x reference)
#include <cuda_runtime.h>
#include <cuda_fp16.h>

// ---------------------------------------------------------------------------
// UNetV2 on GB300: gather-HMMA-scatter submanifold conv.
//  - warp GEMM = mma.sync.m16n8k16 (f16 in, f32 acc), features staged fp16
//  - fp16x2 atomic neighbor accumulators, center tap fused into epilogue
//  - per-slice memsets + bot-half nb conv forked onto side streams
// ---------------------------------------------------------------------------

#define MAXN 500000
#define NC   32
#define SEG  16384
#define NBK  26
#define BLKSEG 64
#define ASTRIDE ((size_t)(MAXN + 1) * NC)
#define ACCBYTES (ASTRIDE * sizeof(__half))
#define ROWB 80                      // smem row stride (bytes) per entry

static __device__ __half g_acc[4 * ASTRIDE];
static __device__ __half g_h1[MAXN * NC];
static __device__ __half g_h2[MAXN * NC];
static __device__ __half g_h3[MAXN * NC];
static __device__ int2   g_rb[NBK * SEG];
static __device__ int    g_kcnt[32];

__device__ __forceinline__ unsigned cvt_h2(float lo, float hi) {
    unsigned r;
    asm("cvt.rn.f16x2.f32 %0, %1, %2;" : "=r"(r) : "f"(hi), "f"(lo));
    return r;
}
__device__ __forceinline__ void redadd_h2(__half* p, unsigned hv) {
    asm volatile("red.global.add.noftz.f16x2 [%0], %1;" :: "l"(p), "r"(hv) : "memory");
}
__device__ __forceinline__ void storepair(float* p, float y0, float y1) {
    *(float2*)p = make_float2(y0, y1);
}
__device__ __forceinline__ void storepair(__half* p, float y0, float y1) {
    *(__half2*)p = __floats2half2_rn(y0, y1);
}

// ---------------------------------------------------------------------------
// stage one 32-channel feature row as fp16 into smem row r (swizzled chunks)
// ---------------------------------------------------------------------------
__device__ __forceinline__ void stage_row(char* wbase, int r, const __half* row) {
    const uint4* s = (const uint4*)row;
    int sw = (r >> 3) & 3;
    char* rb = wbase + r * ROWB;
    #pragma unroll
    for (int c = 0; c < 4; ++c)
        *(uint4*)(rb + ((c ^ sw) << 4)) = __ldg(s + c);
}
__device__ __forceinline__ void stage_row(char* wbase, int r, const float* row) {
    const float4* s = (const float4*)row;
    int sw = (r >> 3) & 3;
    char* rb = wbase + r * ROWB;
    #pragma unroll
    for (int c = 0; c < 4; ++c) {
        float4 f0 = __ldg(s + 2 * c);
        float4 f1 = __ldg(s + 2 * c + 1);
        uint4 v;
        v.x = cvt_h2(f0.x, f0.y); v.y = cvt_h2(f0.z, f0.w);
        v.z = cvt_h2(f1.x, f1.y); v.w = cvt_h2(f1.z, f1.w);
        *(uint4*)(rb + ((c ^ sw) << 4)) = v;
    }
}

// ldmatrix.x4: A fragment (16x16 f16) for m-tile mt, k-block kb
__device__ __forceinline__ void ldmA(unsigned a[4], const char* wbase, int mt,
                                     int kb, int lane) {
    int r  = mt * 16 + (lane & 15);
    int lc = 2 * kb + (lane >> 4);
    unsigned addr = (unsigned)__cvta_generic_to_shared(
        wbase + r * ROWB + ((lc ^ ((r >> 3) & 3)) << 4));
    asm volatile("ldmatrix.sync.aligned.m8n8.x4.shared.b16 {%0,%1,%2,%3}, [%4];"
                 : "=r"(a[0]), "=r"(a[1]), "=r"(a[2]), "=r"(a[3]) : "r"(addr));
}

__device__ __forceinline__ void mma16816(float d[4], const unsigned a[4],
                                         const unsigned b[2]) {
    asm volatile(
        "mma.sync.aligned.m16n8k16.row.col.f32.f16.f16.f32 "
        "{%0,%1,%2,%3},{%4,%5,%6,%7},{%8,%9},{%0,%1,%2,%3};"
        : "+f"(d[0]), "+f"(d[1]), "+f"(d[2]), "+f"(d[3])
        : "r"(a[0]), "r"(a[1]), "r"(a[2]), "r"(a[3]), "r"(b[0]), "r"(b[1]));
}

// build B fragments from fp32 weights Wk[cin][cout]: bf[nb][kb][2]
__device__ __forceinline__ void buildB(unsigned bf[4][2][2], const float* Wk,
                                       int lane) {
    int g = lane >> 2, t = lane & 3;
    #pragma unroll
    for (int nb = 0; nb < 4; ++nb) {
        int nn = nb * 8 + g;
        #pragma unroll
        for (int kb = 0; kb < 2; ++kb) {
            int k0 = 16 * kb + 2 * t;
            bf[nb][kb][0] = cvt_h2(__ldg(Wk + k0 * 32 + nn),
                                   __ldg(Wk + (k0 + 1) * 32 + nn));
            bf[nb][kb][1] = cvt_h2(__ldg(Wk + (k0 + 8) * 32 + nn),
                                   __ldg(Wk + (k0 + 9) * 32 + nn));
        }
    }
}

// ---------------------------------------------------------------------------
__global__ __launch_bounds__(256)
void build_rb(const int* __restrict__ nbr, int n)
{
    __shared__ int nsh[256 * 27];
    const int tid  = threadIdx.x;
    const int lane = tid & 31;
    const long long base = (long long)blockIdx.x * 256;

    for (int i = tid; i < 256 * 27; i += 256) {
        long long g = base * 27 + i;
        nsh[i] = (g < (long long)n * 27) ? nbr[g] : n;
    }
    __syncthreads();

    const int v = (int)(base + tid);
    const bool live = v < n;

    #pragma unroll 1
    for (int j = 0; j < NBK; ++j) {
        int k = (j < 13) ? j : j + 1;
        int u = nsh[tid * 27 + k];
        bool want = live && ((unsigned)u < (unsigned)n);
        unsigned m = __ballot_sync(0xffffffffu, want);
        int rank = __popc(m & ((1u << lane) - 1));
        int leader = (m != 0u) ? (__ffs(m) - 1) : 0;
        int bp = 0;
        if (m != 0u && lane == leader) bp = atomicAdd(&g_kcnt[j], __popc(m));
        bp = __shfl_sync(0xffffffffu, bp, leader);
        int pos = bp + rank;
        if (want && pos < SEG) g_rb[j * SEG + pos] = make_int2(v, u);
    }
}

// ---------------------------------------------------------------------------
// neighbor taps via HMMA: acc[v] += Wk^T x[u]
// ---------------------------------------------------------------------------
template <typename T>
__global__ __launch_bounds__(256)
void nb_conv(const T* __restrict__ x, const float* __restrict__ W,
             int kstride, int hoff, __half* __restrict__ acc, int n)
{
    __shared__ __align__(16) char xsm[8 * 32 * ROWB];
    const int j   = blockIdx.x / BLKSEG;
    const int bis = blockIdx.x % BLKSEG;
    const int cnt = g_kcnt[j];
    if (bis * 256 >= cnt) return;

    const int k = (j < 13) ? j : j + 1;
    const float* Wk = W + (size_t)k * kstride + hoff;

    const int lane = threadIdx.x & 31;
    const int warp = threadIdx.x >> 5;
    const int g = lane >> 2, t = lane & 3;

    unsigned bf[4][2][2];
    buildB(bf, Wk, lane);

    const int eidx = bis * 256 + warp * 32 + lane;
    int2 e = (eidx < cnt) ? __ldg(&g_rb[j * SEG + eidx]) : make_int2(n, 0);

    char* wb = xsm + warp * (32 * ROWB);
    stage_row(wb, lane, x + (size_t)e.y * 32);
    __syncwarp();

    #pragma unroll
    for (int mt = 0; mt < 2; ++mt) {
        unsigned a[2][4];
        ldmA(a[0], wb, mt, 0, lane);
        ldmA(a[1], wb, mt, 1, lane);
        float d[4][4] = {};
        #pragma unroll
        for (int nb = 0; nb < 4; ++nb) {
            mma16816(d[nb], a[0], bf[nb][0]);
            mma16816(d[nb], a[1], bf[nb][1]);
        }
        int v1 = __shfl_sync(0xffffffffu, e.x, mt * 16 + g);
        int v2 = __shfl_sync(0xffffffffu, e.x, mt * 16 + g + 8);
        #pragma unroll
        for (int nb = 0; nb < 4; ++nb) {
            int c0 = nb * 8 + 2 * t;
            redadd_h2(acc + (size_t)v1 * 32 + c0, cvt_h2(d[nb][0], d[nb][1]));
            redadd_h2(acc + (size_t)v2 * 32 + c0, cvt_h2(d[nb][2], d[nb][3]));
        }
    }
}

// ---------------------------------------------------------------------------
// epilogue via HMMA with fused center tap:
//   conv = acc[v] + Wc0^T x0[v] (+ Wc1^T x1[v] for MODE 2)
//   MODE 0: y = relu(bn(conv)); 1: +res before relu; 2: +xred(cat(x0,x1)) after
// ---------------------------------------------------------------------------
template <int MODE, typename T0, typename TOUT>
__global__ __launch_bounds__(256)
void epi(const __half* __restrict__ acc, const float* __restrict__ bnp,
         const T0* __restrict__ x0, const float* __restrict__ Wc0,
         const __half* __restrict__ x1, const float* __restrict__ Wc1,
         const float* __restrict__ res,
         TOUT* __restrict__ out, int n)
{
    __shared__ __align__(16) char xsm[8 * 64 * ROWB];
    __shared__ float ssm[32], bsm[32];

    const int tid  = threadIdx.x;
    const int lane = tid & 31;
    const int warp = tid >> 5;
    const int g = lane >> 2, t = lane & 3;

    if (tid < 32) {
        float s = __ldg(bnp + tid) * rsqrtf(__ldg(bnp + 96 + tid) + 1e-3f);
        ssm[tid] = s;
        bsm[tid] = __ldg(bnp + 32 + tid) - __ldg(bnp + 64 + tid) * s;
    }
    __syncthreads();

    const int base = (blockIdx.x * 8 + warp) * 32;
    if (base >= n) return;

    char* x0b = xsm + warp * (64 * ROWB);
    char* x1b = x0b + 32 * ROWB;

    {
        int vox = base + lane;
        int uu = (vox < n) ? vox : 0;
        stage_row(x0b, lane, x0 + (size_t)uu * 32);
        if (MODE == 2) stage_row(x1b, lane, x1 + (size_t)uu * 32);
    }
    __syncwarp();

    unsigned bf0[4][2][2];
    buildB(bf0, Wc0, lane);
    unsigned bf1[4][2][2];
    if (MODE == 2) buildB(bf1, Wc1, lane);

    #pragma unroll
    for (int mt = 0; mt < 2; ++mt) {
        unsigned a0[2][4];
        ldmA(a0[0], x0b, mt, 0, lane);
        ldmA(a0[1], x0b, mt, 1, lane);
        float d[4][4] = {};
        #pragma unroll
        for (int nb = 0; nb < 4; ++nb) {
            mma16816(d[nb], a0[0], bf0[nb][0]);
            mma16816(d[nb], a0[1], bf0[nb][1]);
        }
        if (MODE == 2) {
            unsigned a1[2][4];
            ldmA(a1[0], x1b, mt, 0, lane);
            ldmA(a1[1], x1b, mt, 1, lane);
            #pragma unroll
            for (int nb = 0; nb < 4; ++nb) {
                mma16816(d[nb], a1[0], bf1[nb][0]);
                mma16816(d[nb], a1[1], bf1[nb][1]);
            }
        }

        int v1 = base + mt * 16 + g;
        int v2 = v1 + 8;
        int u1 = (v1 < n) ? v1 : 0;
        int u2 = (v2 < n) ? v2 : 0;

        #pragma unroll
        for (int nb = 0; nb < 4; ++nb) {
            int c0 = nb * 8 + 2 * t;
            float s0 = ssm[c0], s1 = ssm[c0 + 1];
            float b0 = bsm[c0], b1 = bsm[c0 + 1];

            #pragma unroll
            for (int rw = 0; rw < 2; ++rw) {
                int u = rw ? u2 : u1;
                int v = rw ? v2 : v1;
                float dv0 = d[nb][rw * 2], dv1 = d[nb][rw * 2 + 1];
                float2 a2 = __half22float2(
                    __ldg((const __half2*)(acc + (size_t)u * 32 + c0)));
                float y0 = (a2.x + dv0) * s0 + b0;
                float y1 = (a2.y + dv1) * s1 + b1;
                if (MODE == 1) {
                    float2 rr = __ldg((const float2*)(res + (size_t)u * 32 + c0));
                    y0 += rr.x; y1 += rr.y;
                }
                y0 = fmaxf(y0, 0.0f);
                y1 = fmaxf(y1, 0.0f);
                if (MODE == 2) {
                    if (nb < 2) {
                        float4 q = __ldg((const float4*)((const float*)x0 +
                                         (size_t)u * 32 + 2 * c0));
                        y0 += q.x + q.y;
                        y1 += q.z + q.w;
                    } else {
                        const __half2* hp = (const __half2*)(x1 +
                                            (size_t)u * 32 + (2 * c0 - 32));
                        float2 qa = __half22float2(__ldg(hp));
                        float2 qb = __half22float2(__ldg(hp + 1));
                        y0 += qa.x + qa.y;
                        y1 += qb.x + qb.y;
                    }
                }
                if (v < n) storepair(out + (size_t)v * 32 + c0, y0, y1);
            }
        }
    }
}

// ---------------------------------------------------------------------------
extern "C" void kernel_launch(void* const* d_in, const int* in_sizes, int n_in,
                              void* d_out, int out_size)
{
    const float* lat  = (const float*)d_in[0];
    const float* bot  = (const float*)d_in[1];
    const float* Wt1  = (const float*)d_in[2];
    const float* bnt1 = (const float*)d_in[3];
    const float* Wt2  = (const float*)d_in[4];
    const float* bnt2 = (const float*)d_in[5];
    const float* Wm   = (const float*)d_in[6];
    const float* bnm  = (const float*)d_in[7];
    const float* Wi   = (const float*)d_in[8];
    const float* bni  = (const float*)d_in[9];
    const int*   nbr  = (const int*)d_in[10];

    const int n = in_sizes[0] / NC;

    __half *accb, *h1, *h2, *h3;
    int* kcnt;
    cudaGetSymbolAddress((void**)&accb, g_acc);
    cudaGetSymbolAddress((void**)&h1, g_h1);
    cudaGetSymbolAddress((void**)&h2, g_h2);
    cudaGetSymbolAddress((void**)&h3, g_h3);
    cudaGetSymbolAddress((void**)&kcnt, g_kcnt);

    __half* a1 = accb;
    __half* a2 = accb + 1 * ASTRIDE;
    __half* a3 = accb + 2 * ASTRIDE;
    __half* a4 = accb + 3 * ASTRIDE;

    static cudaStream_t s1 = nullptr, s2 = nullptr;
    static cudaEvent_t e0 = nullptr, eB = nullptr, e2 = nullptr;
    static cudaEvent_t em1 = nullptr, em2 = nullptr, em3 = nullptr, em4 = nullptr;
    if (!s1) {
        cudaStreamCreateWithFlags(&s1, cudaStreamNonBlocking);
        cudaStreamCreateWithFlags(&s2, cudaStreamNonBlocking);
        cudaEventCreateWithFlags(&e0, cudaEventDisableTiming);
        cudaEventCreateWithFlags(&eB, cudaEventDisableTiming);
        cudaEventCreateWithFlags(&e2, cudaEventDisableTiming);
        cudaEventCreateWithFlags(&em1, cudaEventDisableTiming);
        cudaEventCreateWithFlags(&em2, cudaEventDisableTiming);
        cudaEventCreateWithFlags(&em3, cudaEventDisableTiming);
        cudaEventCreateWithFlags(&em4, cudaEventDisableTiming);
    }

    const int gridC = (n + 255) / 256;
    const int gridN = NBK * BLKSEG;

    cudaMemsetAsync(kcnt, 0, 32 * sizeof(int), 0);
    cudaEventRecord(e0, 0);
    cudaStreamWaitEvent(s1, e0, 0);
    cudaMemsetAsync(a1, 0, ACCBYTES, s1); cudaEventRecord(em1, s1);
    cudaMemsetAsync(a3, 0, ACCBYTES, s1); cudaEventRecord(em3, s1);
    cudaMemsetAsync(a2, 0, ACCBYTES, s1); cudaEventRecord(em2, s1);
    cudaMemsetAsync(a4, 0, ACCBYTES, s1); cudaEventRecord(em4, s1);

    build_rb<<<gridC, 256>>>(nbr, n);
    cudaEventRecord(eB, 0);

    // fork: conv_m's bot-half neighbor pass overlaps conv1/conv2
    cudaStreamWaitEvent(s2, eB, 0);
    cudaStreamWaitEvent(s2, em3, 0);
    nb_conv<float><<<gridN, 256, 0, s2>>>(bot, Wm, 2048, 0, a3, n);
    cudaEventRecord(e2, s2);

    // conv1
    cudaStreamWaitEvent(0, em1, 0);
    nb_conv<float><<<gridN, 256>>>(lat, Wt1, 1024, 0, a1, n);
    epi<0, float, __half><<<gridC, 256>>>(a1, bnt1, lat, Wt1 + 13 * 1024,
                                          nullptr, nullptr, nullptr, h1, n);

    // conv2
    cudaStreamWaitEvent(0, em2, 0);
    nb_conv<__half><<<gridN, 256>>>(h1, Wt2, 1024, 0, a2, n);
    epi<1, __half, __half><<<gridC, 256>>>(a2, bnt2, h1, Wt2 + 13 * 1024,
                                           nullptr, nullptr, lat, h2, n);

    // conv_m
    nb_conv<__half><<<gridN, 256>>>(h2, Wm, 2048, 1024, a3, n);
    cudaStreamWaitEvent(0, e2, 0);
    epi<2, float, __half><<<gridC, 256>>>(a3, bnm, bot, Wm + 13 * 2048,
                                          h2, Wm + 13 * 2048 + 1024, nullptr, h3, n);

    // conv_inv
    cudaStreamWaitEvent(0, em4, 0);
    nb_conv<__half><<<gridN, 256>>>(h3, Wi, 1024, 0, a4, n);
    epi<0, __half, float><<<gridC, 256>>>(a4, bni, h3, Wi + 13 * 1024,
                                          nullptr, nullptr, nullptr, (float*)d_out, n);
}

// round 10
// speedup vs baseline: 1.3270x; 1.3270x over previous
#include <cuda_runtime.h>
#include <cuda_fp16.h>

// ---------------------------------------------------------------------------
// UNetV2 on GB300, hybrid:
//  - nb_conv: FMA f32x2 pipeline, shuffle-staged coalesced gathers,
//    lane=cout, coalesced fp16x2 atomics (best measured: R8)
//  - epi: HMMA m16n8k16 with fused center tap (best measured: R9)
//  - per-slice memsets + bot-half nb conv forked onto side streams
// ---------------------------------------------------------------------------

#define MAXN 500000
#define NC   32
#define SEG  16384
#define NBK  26
#define BLKSEG 64
#define ASTRIDE ((size_t)(MAXN + 1) * NC)
#define ACCBYTES (ASTRIDE * sizeof(__half))
#define ROWB 80

static __device__ __half g_acc[4 * ASTRIDE];
static __device__ __half g_h1[MAXN * NC];
static __device__ __half g_h2[MAXN * NC];
static __device__ __half g_h3[MAXN * NC];
static __device__ int2   g_rb[NBK * SEG];
static __device__ int    g_kcnt[32];

typedef unsigned long long u64;

__device__ __forceinline__ u64 splat2(float a) {
    u64 r; asm("mov.b64 %0, {%1, %1};" : "=l"(r) : "f"(a)); return r;
}
__device__ __forceinline__ u64 pack2(float a, float b) {
    u64 r; asm("mov.b64 %0, {%1, %2};" : "=l"(r) : "f"(a), "f"(b)); return r;
}
__device__ __forceinline__ void fma2(u64& d, u64 a, u64 b) {
    asm("fma.rn.f32x2 %0, %1, %2, %3;" : "=l"(d) : "l"(a), "l"(b), "l"(d));
}
__device__ __forceinline__ float2 unpack2(u64 a) {
    float2 r; asm("mov.b64 {%0, %1}, %2;" : "=f"(r.x), "=f"(r.y) : "l"(a)); return r;
}
__device__ __forceinline__ unsigned cvt_h2(float lo, float hi) {
    unsigned r;
    asm("cvt.rn.f16x2.f32 %0, %1, %2;" : "=r"(r) : "f"(hi), "f"(lo));
    return r;
}
__device__ __forceinline__ void redadd_h2(__half* p, unsigned hv) {
    asm volatile("red.global.add.noftz.f16x2 [%0], %1;" :: "l"(p), "r"(hv) : "memory");
}
__device__ __forceinline__ float loadf(const float* p)  { return __ldg(p); }
__device__ __forceinline__ float loadf(const __half* p) { return __half2float(__ldg(p)); }
__device__ __forceinline__ void storepair(float* p, float y0, float y1) {
    *(float2*)p = make_float2(y0, y1);
}
__device__ __forceinline__ void storepair(__half* p, float y0, float y1) {
    *(__half2*)p = __floats2half2_rn(y0, y1);
}

// ---------------------------------------------------------------------------
// HMMA helpers (epi)
// ---------------------------------------------------------------------------
__device__ __forceinline__ void stage_row(char* wbase, int r, const __half* row) {
    const uint4* s = (const uint4*)row;
    int sw = (r >> 3) & 3;
    char* rb = wbase + r * ROWB;
    #pragma unroll
    for (int c = 0; c < 4; ++c)
        *(uint4*)(rb + ((c ^ sw) << 4)) = __ldg(s + c);
}
__device__ __forceinline__ void stage_row(char* wbase, int r, const float* row) {
    const float4* s = (const float4*)row;
    int sw = (r >> 3) & 3;
    char* rb = wbase + r * ROWB;
    #pragma unroll
    for (int c = 0; c < 4; ++c) {
        float4 f0 = __ldg(s + 2 * c);
        float4 f1 = __ldg(s + 2 * c + 1);
        uint4 v;
        v.x = cvt_h2(f0.x, f0.y); v.y = cvt_h2(f0.z, f0.w);
        v.z = cvt_h2(f1.x, f1.y); v.w = cvt_h2(f1.z, f1.w);
        *(uint4*)(rb + ((c ^ sw) << 4)) = v;
    }
}

__device__ __forceinline__ void ldmA(unsigned a[4], const char* wbase, int mt,
                                     int kb, int lane) {
    int r  = mt * 16 + (lane & 15);
    int lc = 2 * kb + (lane >> 4);
    unsigned addr = (unsigned)__cvta_generic_to_shared(
        wbase + r * ROWB + ((lc ^ ((r >> 3) & 3)) << 4));
    asm volatile("ldmatrix.sync.aligned.m8n8.x4.shared.b16 {%0,%1,%2,%3}, [%4];"
                 : "=r"(a[0]), "=r"(a[1]), "=r"(a[2]), "=r"(a[3]) : "r"(addr));
}

__device__ __forceinline__ void mma16816(float d[4], const unsigned a[4],
                                         const unsigned b[2]) {
    asm volatile(
        "mma.sync.aligned.m16n8k16.row.col.f32.f16.f16.f32 "
        "{%0,%1,%2,%3},{%4,%5,%6,%7},{%8,%9},{%0,%1,%2,%3};"
        : "+f"(d[0]), "+f"(d[1]), "+f"(d[2]), "+f"(d[3])
        : "r"(a[0]), "r"(a[1]), "r"(a[2]), "r"(a[3]), "r"(b[0]), "r"(b[1]));
}

__device__ __forceinline__ void buildB(unsigned bf[4][2][2], const float* Wk,
                                       int lane) {
    int g = lane >> 2, t = lane & 3;
    #pragma unroll
    for (int nb = 0; nb < 4; ++nb) {
        int nn = nb * 8 + g;
        #pragma unroll
        for (int kb = 0; kb < 2; ++kb) {
            int k0 = 16 * kb + 2 * t;
            bf[nb][kb][0] = cvt_h2(__ldg(Wk + k0 * 32 + nn),
                                   __ldg(Wk + (k0 + 1) * 32 + nn));
            bf[nb][kb][1] = cvt_h2(__ldg(Wk + (k0 + 8) * 32 + nn),
                                   __ldg(Wk + (k0 + 9) * 32 + nn));
        }
    }
}

// ---------------------------------------------------------------------------
__global__ __launch_bounds__(256)
void build_rb(const int* __restrict__ nbr, int n)
{
    __shared__ int nsh[256 * 27];
    const int tid  = threadIdx.x;
    const int lane = tid & 31;
    const long long base = (long long)blockIdx.x * 256;

    for (int i = tid; i < 256 * 27; i += 256) {
        long long g = base * 27 + i;
        nsh[i] = (g < (long long)n * 27) ? nbr[g] : n;
    }
    __syncthreads();

    const int v = (int)(base + tid);
    const bool live = v < n;

    #pragma unroll 1
    for (int j = 0; j < NBK; ++j) {
        int k = (j < 13) ? j : j + 1;
        int u = nsh[tid * 27 + k];
        bool want = live && ((unsigned)u < (unsigned)n);
        unsigned m = __ballot_sync(0xffffffffu, want);
        int rank = __popc(m & ((1u << lane) - 1));
        int leader = (m != 0u) ? (__ffs(m) - 1) : 0;
        int bp = 0;
        if (m != 0u && lane == leader) bp = atomicAdd(&g_kcnt[j], __popc(m));
        bp = __shfl_sync(0xffffffffu, bp, leader);
        int pos = bp + rank;
        if (want && pos < SEG) g_rb[j * SEG + pos] = make_int2(v, u);
    }
}

// ---------------------------------------------------------------------------
// FMA pair GEMM (nb_conv)
// ---------------------------------------------------------------------------
__device__ __forceinline__ void pair_gemm(const u64* f, const u64* wsp, int p,
                                          float& rA, float& rB)
{
    const ulonglong2* row = (const ulonglong2*)(f + p * 32);
    u64 aE = 0ull, aO = 0ull;
    #pragma unroll
    for (int c2 = 0; c2 < 16; ++c2) {
        ulonglong2 q = row[c2];
        fma2(aE, q.x, wsp[2 * c2]);
        fma2(aO, q.y, wsp[2 * c2 + 1]);
    }
    float2 e = unpack2(aE), o = unpack2(aO);
    rA = e.x + o.x;
    rB = e.y + o.y;
}

// ---------------------------------------------------------------------------
// neighbor taps: FMA pipeline, coalesced fp16x2 atomics (round-8 form)
// ---------------------------------------------------------------------------
template <typename T>
__global__ __launch_bounds__(256)
void nb_conv(const T* __restrict__ x, const float* __restrict__ W,
             int kstride, int hoff, __half* __restrict__ acc, int n)
{
    __shared__ u64 ft[8 * 512];
    const int j   = blockIdx.x / BLKSEG;
    const int bis = blockIdx.x % BLKSEG;
    const int cnt = g_kcnt[j];
    if (bis * 256 >= cnt) return;

    const int k = (j < 13) ? j : j + 1;
    const float* Wk = W + (size_t)k * kstride + hoff;

    const int lane = threadIdx.x & 31;
    const int warp = threadIdx.x >> 5;

    u64 wsp[32];
    #pragma unroll
    for (int c = 0; c < 32; ++c) wsp[c] = splat2(__ldg(Wk + c * 32 + lane));

    const int eidx = bis * 256 + warp * 32 + lane;
    int2 e = (eidx < cnt) ? __ldg(&g_rb[j * SEG + eidx]) : make_int2(n, 0);

    u64* f = ft + warp * 512;
    #pragma unroll 4
    for (int p = 0; p < 16; ++p) {
        int uA = __shfl_sync(0xffffffffu, e.y, 2 * p);
        int uB = __shfl_sync(0xffffffffu, e.y, 2 * p + 1);
        f[p * 32 + lane] = pack2(loadf(x + (size_t)uA * 32 + lane),
                                 loadf(x + (size_t)uB * 32 + lane));
    }
    __syncwarp();

    #pragma unroll 2
    for (int p = 0; p < 16; ++p) {
        float rA, rB;
        pair_gemm(f, wsp, p, rA, rB);
        int vA = __shfl_sync(0xffffffffu, e.x, 2 * p);
        int vB = __shfl_sync(0xffffffffu, e.x, 2 * p + 1);
        float pA = __shfl_xor_sync(0xffffffffu, rA, 1);
        float pB = __shfl_xor_sync(0xffffffffu, rB, 1);
        unsigned hv;
        int v;
        if ((lane & 1) == 0) { hv = cvt_h2(rA, pA); v = vA; }
        else                 { hv = cvt_h2(pB, rB); v = vB; }
        redadd_h2(acc + (size_t)v * 32 + (lane & ~1), hv);
    }
}

// ---------------------------------------------------------------------------
// epilogue via HMMA with fused center tap (round-9 form)
// ---------------------------------------------------------------------------
template <int MODE, typename T0, typename TOUT>
__global__ __launch_bounds__(256)
void epi(const __half* __restrict__ acc, const float* __restrict__ bnp,
         const T0* __restrict__ x0, const float* __restrict__ Wc0,
         const __half* __restrict__ x1, const float* __restrict__ Wc1,
         const float* __restrict__ res,
         TOUT* __restrict__ out, int n)
{
    __shared__ __align__(16) char xsm[8 * 64 * ROWB];
    __shared__ float ssm[32], bsm[32];

    const int tid  = threadIdx.x;
    const int lane = tid & 31;
    const int warp = tid >> 5;
    const int g = lane >> 2, t = lane & 3;

    if (tid < 32) {
        float s = __ldg(bnp + tid) * rsqrtf(__ldg(bnp + 96 + tid) + 1e-3f);
        ssm[tid] = s;
        bsm[tid] = __ldg(bnp + 32 + tid) - __ldg(bnp + 64 + tid) * s;
    }
    __syncthreads();

    const int base = (blockIdx.x * 8 + warp) * 32;
    if (base >= n) return;

    char* x0b = xsm + warp * (64 * ROWB);
    char* x1b = x0b + 32 * ROWB;

    {
        int vox = base + lane;
        int uu = (vox < n) ? vox : 0;
        stage_row(x0b, lane, x0 + (size_t)uu * 32);
        if (MODE == 2) stage_row(x1b, lane, x1 + (size_t)uu * 32);
    }
    __syncwarp();

    unsigned bf0[4][2][2];
    buildB(bf0, Wc0, lane);
    unsigned bf1[4][2][2];
    if (MODE == 2) buildB(bf1, Wc1, lane);

    #pragma unroll
    for (int mt = 0; mt < 2; ++mt) {
        unsigned a0[2][4];
        ldmA(a0[0], x0b, mt, 0, lane);
        ldmA(a0[1], x0b, mt, 1, lane);
        float d[4][4] = {};
        #pragma unroll
        for (int nb = 0; nb < 4; ++nb) {
            mma16816(d[nb], a0[0], bf0[nb][0]);
            mma16816(d[nb], a0[1], bf0[nb][1]);
        }
        if (MODE == 2) {
            unsigned a1[2][4];
            ldmA(a1[0], x1b, mt, 0, lane);
            ldmA(a1[1], x1b, mt, 1, lane);
            #pragma unroll
            for (int nb = 0; nb < 4; ++nb) {
                mma16816(d[nb], a1[0], bf1[nb][0]);
                mma16816(d[nb], a1[1], bf1[nb][1]);
            }
        }

        int v1 = base + mt * 16 + g;
        int v2 = v1 + 8;
        int u1 = (v1 < n) ? v1 : 0;
        int u2 = (v2 < n) ? v2 : 0;

        #pragma unroll
        for (int nb = 0; nb < 4; ++nb) {
            int c0 = nb * 8 + 2 * t;
            float s0 = ssm[c0], s1 = ssm[c0 + 1];
            float b0 = bsm[c0], b1 = bsm[c0 + 1];

            #pragma unroll
            for (int rw = 0; rw < 2; ++rw) {
                int u = rw ? u2 : u1;
                int v = rw ? v2 : v1;
                float dv0 = d[nb][rw * 2], dv1 = d[nb][rw * 2 + 1];
                float2 a2 = __half22float2(
                    __ldg((const __half2*)(acc + (size_t)u * 32 + c0)));
                float y0 = (a2.x + dv0) * s0 + b0;
                float y1 = (a2.y + dv1) * s1 + b1;
                if (MODE == 1) {
                    float2 rr = __ldg((const float2*)(res + (size_t)u * 32 + c0));
                    y0 += rr.x; y1 += rr.y;
                }
                y0 = fmaxf(y0, 0.0f);
                y1 = fmaxf(y1, 0.0f);
                if (MODE == 2) {
                    if (nb < 2) {
                        float4 q = __ldg((const float4*)((const float*)x0 +
                                         (size_t)u * 32 + 2 * c0));
                        y0 += q.x + q.y;
                        y1 += q.z + q.w;
                    } else {
                        const __half2* hp = (const __half2*)(x1 +
                                            (size_t)u * 32 + (2 * c0 - 32));
                        float2 qa = __half22float2(__ldg(hp));
                        float2 qb = __half22float2(__ldg(hp + 1));
                        y0 += qa.x + qa.y;
                        y1 += qb.x + qb.y;
                    }
                }
                if (v < n) storepair(out + (size_t)v * 32 + c0, y0, y1);
            }
        }
    }
}

// ---------------------------------------------------------------------------
extern "C" void kernel_launch(void* const* d_in, const int* in_sizes, int n_in,
                              void* d_out, int out_size)
{
    const float* lat  = (const float*)d_in[0];
    const float* bot  = (const float*)d_in[1];
    const float* Wt1  = (const float*)d_in[2];
    const float* bnt1 = (const float*)d_in[3];
    const float* Wt2  = (const float*)d_in[4];
    const float* bnt2 = (const float*)d_in[5];
    const float* Wm   = (const float*)d_in[6];
    const float* bnm  = (const float*)d_in[7];
    const float* Wi   = (const float*)d_in[8];
    const float* bni  = (const float*)d_in[9];
    const int*   nbr  = (const int*)d_in[10];

    const int n = in_sizes[0] / NC;

    __half *accb, *h1, *h2, *h3;
    int* kcnt;
    cudaGetSymbolAddress((void**)&accb, g_acc);
    cudaGetSymbolAddress((void**)&h1, g_h1);
    cudaGetSymbolAddress((void**)&h2, g_h2);
    cudaGetSymbolAddress((void**)&h3, g_h3);
    cudaGetSymbolAddress((void**)&kcnt, g_kcnt);

    __half* a1 = accb;
    __half* a2 = accb + 1 * ASTRIDE;
    __half* a3 = accb + 2 * ASTRIDE;
    __half* a4 = accb + 3 * ASTRIDE;

    static cudaStream_t s1 = nullptr, s2 = nullptr;
    static cudaEvent_t e0 = nullptr, eB = nullptr, e2 = nullptr;
    static cudaEvent_t em1 = nullptr, em2 = nullptr, em3 = nullptr, em4 = nullptr;
    if (!s1) {
        cudaStreamCreateWithFlags(&s1, cudaStreamNonBlocking);
        cudaStreamCreateWithFlags(&s2, cudaStreamNonBlocking);
        cudaEventCreateWithFlags(&e0, cudaEventDisableTiming);
        cudaEventCreateWithFlags(&eB, cudaEventDisableTiming);
        cudaEventCreateWithFlags(&e2, cudaEventDisableTiming);
        cudaEventCreateWithFlags(&em1, cudaEventDisableTiming);
        cudaEventCreateWithFlags(&em2, cudaEventDisableTiming);
        cudaEventCreateWithFlags(&em3, cudaEventDisableTiming);
        cudaEventCreateWithFlags(&em4, cudaEventDisableTiming);
    }

    const int gridC = (n + 255) / 256;
    const int gridN = NBK * BLKSEG;

    cudaMemsetAsync(kcnt, 0, 32 * sizeof(int), 0);
    cudaEventRecord(e0, 0);
    cudaStreamWaitEvent(s1, e0, 0);
    cudaMemsetAsync(a1, 0, ACCBYTES, s1); cudaEventRecord(em1, s1);
    cudaMemsetAsync(a3, 0, ACCBYTES, s1); cudaEventRecord(em3, s1);
    cudaMemsetAsync(a2, 0, ACCBYTES, s1); cudaEventRecord(em2, s1);
    cudaMemsetAsync(a4, 0, ACCBYTES, s1); cudaEventRecord(em4, s1);

    build_rb<<<gridC, 256>>>(nbr, n);
    cudaEventRecord(eB, 0);

    // fork: conv_m's bot-half neighbor pass overlaps conv1/conv2
    cudaStreamWaitEvent(s2, eB, 0);
    cudaStreamWaitEvent(s2, em3, 0);
    nb_conv<float><<<gridN, 256, 0, s2>>>(bot, Wm, 2048, 0, a3, n);
    cudaEventRecord(e2, s2);

    // conv1
    cudaStreamWaitEvent(0, em1, 0);
    nb_conv<float><<<gridN, 256>>>(lat, Wt1, 1024, 0, a1, n);
    epi<0, float, __half><<<gridC, 256>>>(a1, bnt1, lat, Wt1 + 13 * 1024,
                                          nullptr, nullptr, nullptr, h1, n);

    // conv2
    cudaStreamWaitEvent(0, em2, 0);
    nb_conv<__half><<<gridN, 256>>>(h1, Wt2, 1024, 0, a2, n);
    epi<1, __half, __half><<<gridC, 256>>>(a2, bnt2, h1, Wt2 + 13 * 1024,
                                           nullptr, nullptr, lat, h2, n);

    // conv_m
    nb_conv<__half><<<gridN, 256>>>(h2, Wm, 2048, 1024, a3, n);
    cudaStreamWaitEvent(0, e2, 0);
    epi<2, float, __half><<<gridC, 256>>>(a3, bnm, bot, Wm + 13 * 2048,
                                          h2, Wm + 13 * 2048 + 1024, nullptr, h3, n);

    // conv_inv
    cudaStreamWaitEvent(0, em4, 0);
    nb_conv<__half><<<gridN, 256>>>(h3, Wi, 1024, 0, a4, n);
    epi<0, __half, float><<<gridC, 256>>>(a4, bni, h3, Wi + 13 * 1024,
                                          nullptr, nullptr, nullptr, (float*)d_out, n);
}